// round 9
// baseline (speedup 1.0000x reference)
#include <cuda_runtime.h>
#include <math.h>

#define D        64
#define MQ       32
#define TK       64
#define TOPK     32
#define THREADS  768
#define NEG_INF  (-3.402823466e38f)

typedef unsigned long long u64;

struct __align__(16) Smem {
    float Qs[MQ][D + 4];          // pre-scaled q [q][d]
    float Ks[2][TK][D + 4];       // double-buffered k tile
    float Vs[2][TK][D];           // double-buffered v tile
    float Ss[2][MQ][D + 4];       // double-buffered scores; Ss[0] reused for sums
    float tsc[MQ][TOPK];
    int   tix[MQ][TOPK];
    u64   Mbits[2][MQ];
    u64   cand[2][MQ];
    float thr[MQ];
    float cnt[MQ];
};

__device__ __forceinline__ void fma2(u64& d, u64 a, u64 b) {
    asm("fma.rn.f32x2 %0, %1, %2, %0;" : "+l"(d) : "l"(a), "l"(b));
}
__device__ __forceinline__ float2 up2(u64 a) {
    float2 r;
    asm("mov.b64 {%0,%1}, %2;" : "=f"(r.x), "=f"(r.y) : "l"(a));
    return r;
}
__device__ __forceinline__ void madd2(u64& a0, u64& a1, unsigned t, u64 vx, u64 vy) {
    asm volatile("{\n\t.reg .pred p;\n\tsetp.ne.u32 p, %2, 0;\n\t"
                 "@p add.rn.f32x2 %0, %0, %3;\n\t"
                 "@p add.rn.f32x2 %1, %1, %4;\n\t}"
                 : "+l"(a0), "+l"(a1) : "r"(t), "l"(vx), "l"(vy));
}
__device__ __forceinline__ void cp16(void* s, const void* g) {
    unsigned sa = (unsigned)__cvta_generic_to_shared(s);
    asm volatile("cp.async.cg.shared.global [%0], [%1], 16;" :: "r"(sa), "l"(g));
}

__global__ __launch_bounds__(THREADS)
void ga_kernel(const float* __restrict__ q, const float* __restrict__ k,
               const float* __restrict__ v, const int* __restrict__ mask,
               float* __restrict__ out, int B, int Lq, int L)
{
    extern __shared__ unsigned char smem_raw[];
    Smem* S = reinterpret_cast<Smem*>(smem_raw);

    const int tid  = threadIdx.x;
    const int b    = blockIdx.y;
    const int q0g  = blockIdx.x * MQ;
    const int row0 = b * Lq + q0g;
    const int NT   = L / TK;

    const int t15 = tid & 15;
    // score warps 0-7 (tid < 256): thread tile 2q x 4k, strided k rows
    const int qa = 2 * ((tid & 255) >> 4);
    // V warps 8-19 (tid 256..639): 3-way l-split, thread tile 4q x 4d
    const int vidx  = tid - 256;                // 0..383
    const int vgrp  = vidx >> 7;                // 0,1,2
    const int w128  = vidx & 127;
    const int qb    = 4 * (w128 >> 4);
    const int dc    = 4 * (w128 & 15);
    const int lbase = 21 * vgrp;                // 0, 21, 42
    const int lcnt  = (vgrp == 2) ? 22 : 21;

    // ---- init ----
    for (int j = tid; j < MQ * D; j += THREADS) {
        int qi = j >> 6, d = j & 63;
        S->Qs[qi][d] = q[((size_t)row0 + qi) * D + d] * 0.125f;
    }
    for (int j = tid; j < MQ * TOPK; j += THREADS) {
        S->tsc[j >> 5][j & 31] = NEG_INF;
        S->tix[j >> 5][j & 31] = -1;
    }
    if (tid < MQ) {
        S->thr[tid]     = NEG_INF;
        S->cand[0][tid] = 0ull;
        S->cand[1][tid] = 0ull;
    }

    const size_t kb = (size_t)b * L * D;

    // ---- prologue: load tile 0 synchronously + Mbits[0] ----
    for (int j = tid; j < 1024; j += THREADS) {
        int i  = j >> 4;
        int c4 = (j & 15) << 2;
        *(float4*)&S->Ks[0][i][c4] = *(const float4*)(k + kb + (size_t)i * D + c4);
        *(float4*)&S->Vs[0][i][c4] = *(const float4*)(v + kb + (size_t)i * D + c4);
    }
    if (tid < 512) {
        int qi = tid >> 4, c4 = (tid & 15) << 2;
        int4 mm = *(const int4*)(mask + (size_t)(row0 + qi) * L + c4);
        u64 bits = ((u64)(mm.x != 0) << c4)       | ((u64)(mm.y != 0) << (c4 + 1))
                 | ((u64)(mm.z != 0) << (c4 + 2)) | ((u64)(mm.w != 0) << (c4 + 3));
        #pragma unroll
        for (int off = 1; off < 16; off <<= 1)
            bits |= __shfl_xor_sync(0xFFFFFFFFu, bits, off);
        if ((tid & 15) == 0) S->Mbits[0][qi] = bits;
    }
    __syncthreads();

    u64 mv[8];                                  // V partial accumulators (4q x 4d)
    #pragma unroll
    for (int i = 0; i < 8; i++) mv[i] = 0ull;

    float thrL = NEG_INF;                       // merge warp state
    int   minpos = 0;
    float cntL = 0.0f;

    for (int t = 0; t < NT; t++) {
        const int p  = t & 1;
        const int pn = p ^ 1;
        const int l0 = t * TK;

        if (tid < 256) {
            // ======== score warps: 2q x 4k, strided k rows ========
            const float thr0 = S->thr[qa];
            const float thr1 = S->thr[qa + 1];
            const u64   Mb0  = S->Mbits[p][qa];
            const u64   Mb1  = S->Mbits[p][qa + 1];
            u64 sp0[4], sp1[4];
            #pragma unroll
            for (int j = 0; j < 4; j++) { sp0[j] = 0ull; sp1[j] = 0ull; }

            #pragma unroll 4
            for (int d = 0; d < D; d += 4) {
                ulonglong2 Q0 = *(const ulonglong2*)&S->Qs[qa][d];
                ulonglong2 Q1 = *(const ulonglong2*)&S->Qs[qa + 1][d];
                #pragma unroll
                for (int j = 0; j < 4; j++) {
                    ulonglong2 Kj = *(const ulonglong2*)&S->Ks[p][t15 + 16 * j][d];
                    fma2(sp0[j], Q0.x, Kj.x);
                    fma2(sp0[j], Q0.y, Kj.y);
                    fma2(sp1[j], Q1.x, Kj.x);
                    fma2(sp1[j], Q1.y, Kj.y);
                }
            }
            u64 w0 = 0ull, w1 = 0ull;
            #pragma unroll
            for (int j = 0; j < 4; j++) {
                int kp = t15 + 16 * j;
                float2 p0 = up2(sp0[j]);
                float  s0 = p0.x + p0.y;
                S->Ss[p][qa][kp] = s0;
                if (s0 > thr0 && ((Mb0 >> kp) & 1ull)) w0 |= 1ull << kp;
                float2 p1 = up2(sp1[j]);
                float  s1 = p1.x + p1.y;
                S->Ss[p][qa + 1][kp] = s1;
                if (s1 > thr1 && ((Mb1 >> kp) & 1ull)) w1 |= 1ull << kp;
            }
            if (w0) atomicOr(&S->cand[p][qa],     w0);
            if (w1) atomicOr(&S->cand[p][qa + 1], w1);
        } else if (tid < 640) {
            // ======== V warps: 4q x 4d over ~21-key third ========
            unsigned mw[4];
            #pragma unroll
            for (int qi = 0; qi < 4; qi++)
                mw[qi] = (unsigned)(S->Mbits[p][qb + qi] >> lbase);
            #pragma unroll 7
            for (int l = 0; l < lcnt; l++) {
                ulonglong2 v2 = *(const ulonglong2*)&S->Vs[p][lbase + l][dc];
                #pragma unroll
                for (int qi = 0; qi < 4; qi++) {
                    unsigned tb = mw[qi] & (1u << l);
                    madd2(mv[2 * qi], mv[2 * qi + 1], tb, v2.x, v2.y);
                }
            }
        } else if (tid < 672) {
            // ======== merge warp: consume tile t-1, prefetch mask t+1 ========
            const int qq = tid - 640;
            if (t > 0) {
                u64 w = S->cand[pn][qq];
                S->cand[pn][qq] = 0ull;
                cntL += (float)__popcll(S->Mbits[pn][qq]);
                const int l0p = l0 - TK;
                while (w) {
                    int kk = __ffsll((long long)w) - 1;
                    w &= w - 1ull;
                    float s = S->Ss[pn][qq][kk];
                    if (s > thrL) {
                        S->tsc[qq][minpos] = s;
                        S->tix[qq][minpos] = l0p + kk;
                        float nm = S->tsc[qq][0]; int np = 0;
                        #pragma unroll
                        for (int i = 1; i < TOPK; i++) {
                            float ti = S->tsc[qq][i];
                            if (ti < nm) { nm = ti; np = i; }
                        }
                        thrL = nm; minpos = np;
                    }
                }
                S->thr[qq] = thrL;
            }
            if (t < NT - 1) {
                const int4* mp = (const int4*)(mask + (size_t)(row0 + qq) * L + l0 + TK);
                u64 bits = 0ull;
                #pragma unroll
                for (int c4 = 0; c4 < 16; c4++) {
                    int4 mm = mp[c4];
                    bits |= ((u64)(mm.x != 0) << (4 * c4))
                          | ((u64)(mm.y != 0) << (4 * c4 + 1))
                          | ((u64)(mm.z != 0) << (4 * c4 + 2))
                          | ((u64)(mm.w != 0) << (4 * c4 + 3));
                }
                S->Mbits[pn][qq] = bits;
            }
        } else {
            // ======== loader warps: cp.async next K/V tile ========
            if (t < NT - 1) {
                const int lt = tid - 672;                  // 0..95
                const size_t base = kb + (size_t)(l0 + TK) * D;
                for (int j = lt; j < 2048; j += 96) {
                    int jj = j & 1023;
                    int i  = jj >> 4;
                    int c4 = (jj & 15) << 2;
                    if (j < 1024) cp16(&S->Ks[pn][i][c4], k + base + (size_t)i * D + c4);
                    else          cp16(&S->Vs[pn][i][c4], v + base + (size_t)i * D + c4);
                }
                asm volatile("cp.async.commit_group;");
                asm volatile("cp.async.wait_group 0;");
            }
        }
        __syncthreads();
    }

    // ---- final merge (last tile) ----
    if (tid >= 640 && tid < 672) {
        const int qq = tid - 640;
        const int pl = (NT - 1) & 1;
        u64 w = S->cand[pl][qq];
        cntL += (float)__popcll(S->Mbits[pl][qq]);
        const int l0p = L - TK;
        while (w) {
            int kk = __ffsll((long long)w) - 1;
            w &= w - 1ull;
            float s = S->Ss[pl][qq][kk];
            if (s > thrL) {
                S->tsc[qq][minpos] = s;
                S->tix[qq][minpos] = l0p + kk;
                float nm = S->tsc[qq][0]; int np = 0;
                #pragma unroll
                for (int i = 1; i < TOPK; i++) {
                    float ti = S->tsc[qq][i];
                    if (ti < nm) { nm = ti; np = i; }
                }
                thrL = nm; minpos = np;
            }
        }
        S->cnt[qq] = cntL;
    }
    __syncthreads();   // Ss[] free after this point

    // ---- combine V partials into Ss[0][q][d]: group0 writes, 1 and 2 add ----
    if (tid >= 256 && tid < 384) {
        #pragma unroll
        for (int qi = 0; qi < 4; qi++) {
            float2 a = up2(mv[2 * qi]);
            float2 c = up2(mv[2 * qi + 1]);
            *(float4*)&S->Ss[0][qb + qi][dc] = make_float4(a.x, a.y, c.x, c.y);
        }
    }
    __syncthreads();
    if (tid >= 384 && tid < 512) {
        #pragma unroll
        for (int qi = 0; qi < 4; qi++) {
            float4 cur = *(float4*)&S->Ss[0][qb + qi][dc];
            float2 a = up2(mv[2 * qi]);
            float2 c = up2(mv[2 * qi + 1]);
            cur.x += a.x; cur.y += a.y; cur.z += c.x; cur.w += c.y;
            *(float4*)&S->Ss[0][qb + qi][dc] = cur;
        }
    }
    __syncthreads();
    if (tid >= 512 && tid < 640) {
        #pragma unroll
        for (int qi = 0; qi < 4; qi++) {
            float4 cur = *(float4*)&S->Ss[0][qb + qi][dc];
            float2 a = up2(mv[2 * qi]);
            float2 c = up2(mv[2 * qi + 1]);
            cur.x += a.x; cur.y += a.y; cur.z += c.x; cur.w += c.y;
            *(float4*)&S->Ss[0][qb + qi][dc] = cur;
        }
    }
    __syncthreads();

    // ---- epilogue: softmax over top-32, gather V, add mean ----
    const int wid  = tid >> 5;
    const int lane = tid & 31;
    const float* vb = v + kb;
    for (int qq = wid; qq < MQ; qq += (THREADS / 32)) {
        float s  = S->tsc[qq][lane];
        int   ix = S->tix[qq][lane];
        bool valid = (ix >= 0);
        float sv = valid ? s : NEG_INF;
        float m = sv;
        #pragma unroll
        for (int off = 16; off > 0; off >>= 1)
            m = fmaxf(m, __shfl_xor_sync(0xFFFFFFFFu, m, off));
        float e = valid ? expf(s - m) : 0.0f;
        float den = e;
        #pragma unroll
        for (int off = 16; off > 0; off >>= 1)
            den += __shfl_xor_sync(0xFFFFFFFFu, den, off);
        float w = (den > 0.0f) ? (e / den) : 0.0f;

        float a0 = 0.0f, a1 = 0.0f;
        #pragma unroll 1
        for (int i = 0; i < TOPK; i++) {
            float wi = __shfl_sync(0xFFFFFFFFu, w, i);
            int   ii = __shfl_sync(0xFFFFFFFFu, ix, i);
            if (ii >= 0) {
                const float* vr = vb + (size_t)ii * D;
                a0 = fmaf(wi, vr[lane],      a0);
                a1 = fmaf(wi, vr[lane + 32], a1);
            }
        }
        float c = fmaxf(S->cnt[qq], 1.0f);
        size_t obase = ((size_t)(row0 + qq)) * D;
        out[obase + lane]      = S->Ss[0][qq][lane]      / c + a0;
        out[obase + lane + 32] = S->Ss[0][qq][lane + 32] / c + a1;
    }
}

extern "C" void kernel_launch(void* const* d_in, const int* in_sizes, int n_in,
                              void* d_out, int out_size)
{
    const float* q = (const float*)d_in[0];
    const float* k = (const float*)d_in[1];
    const float* v = (const float*)d_in[2];
    const int*   mask = (const int*)d_in[3];
    float* out = (float*)d_out;

    int N    = in_sizes[0] / D;    // B * Lq
    int Ktot = in_sizes[1] / D;    // B * L
    int L    = in_sizes[3] / N;
    int B    = Ktot / L;
    int Lq   = N / B;

    int smem = (int)sizeof(Smem);
    cudaFuncSetAttribute(ga_kernel, cudaFuncAttributeMaxDynamicSharedMemorySize, smem);

    dim3 grid(Lq / MQ, B);
    ga_kernel<<<grid, THREADS, smem>>>(q, k, v, mask, out, B, Lq, L);
}

// round 10
// speedup vs baseline: 1.7749x; 1.7749x over previous
#include <cuda_runtime.h>
#include <math.h>

#define D        64
#define MQ       32
#define TK       64
#define TOPK     32
#define THREADS  640
#define NEG_INF  (-3.402823466e38f)

typedef unsigned long long u64;

struct __align__(16) Smem {
    float Qs[MQ][D + 4];          // pre-scaled q [q][d]
    float Ks[2][TK][D + 4];       // double-buffered k tile
    float Vs[2][TK][D];           // double-buffered v tile
    float Ss[2][MQ][D + 4];       // double-buffered scores; Ss[0] reused for sums
    float tsc[MQ][TOPK];
    int   tix[MQ][TOPK];
    u64   Mbits[2][MQ];
    u64   cand[2][MQ];
    float thr[MQ];
    float cnt[MQ];
};

__device__ __forceinline__ void fma2(u64& d, u64 a, u64 b) {
    asm("fma.rn.f32x2 %0, %1, %2, %0;" : "+l"(d) : "l"(a), "l"(b));
}
__device__ __forceinline__ float2 up2(u64 a) {
    float2 r;
    asm("mov.b64 {%0,%1}, %2;" : "=f"(r.x), "=f"(r.y) : "l"(a));
    return r;
}
__device__ __forceinline__ void madd2(u64& a0, u64& a1, unsigned t, u64 vx, u64 vy) {
    asm volatile("{\n\t.reg .pred p;\n\tsetp.ne.u32 p, %2, 0;\n\t"
                 "@p add.rn.f32x2 %0, %0, %3;\n\t"
                 "@p add.rn.f32x2 %1, %1, %4;\n\t}"
                 : "+l"(a0), "+l"(a1) : "r"(t), "l"(vx), "l"(vy));
}
__device__ __forceinline__ void cp16(void* s, const void* g) {
    unsigned sa = (unsigned)__cvta_generic_to_shared(s);
    asm volatile("cp.async.cg.shared.global [%0], [%1], 16;" :: "r"(sa), "l"(g));
}

__global__ __launch_bounds__(THREADS)
void ga_kernel(const float* __restrict__ q, const float* __restrict__ k,
               const float* __restrict__ v, const int* __restrict__ mask,
               float* __restrict__ out, int B, int Lq, int L)
{
    extern __shared__ unsigned char smem_raw[];
    Smem* S = reinterpret_cast<Smem*>(smem_raw);

    const int tid  = threadIdx.x;
    const int b    = blockIdx.y;
    const int q0g  = blockIdx.x * MQ;
    const int row0 = b * Lq + q0g;
    const int NT   = L / TK;

    const int t15 = tid & 15;
    // score warps 0-7 (tid < 256): thread tile 2q x 4k, strided k rows
    const int qa = 2 * ((tid & 255) >> 4);
    // V warps 8-15 (tid 256..511): 2-way l-split, thread tile 4q x 4d
    const int vidx  = tid - 256;                // 0..255
    const int vhalf = vidx >> 7;                // 0: keys 0-31, 1: keys 32-63
    const int w128  = vidx & 127;
    const int qb    = 4 * (w128 >> 4);
    const int dc    = 4 * (w128 & 15);

    // ---- init ----
    for (int j = tid; j < MQ * D; j += THREADS) {
        int qi = j >> 6, d = j & 63;
        S->Qs[qi][d] = q[((size_t)row0 + qi) * D + d] * 0.125f;
    }
    for (int j = tid; j < MQ * TOPK; j += THREADS) {
        S->tsc[j >> 5][j & 31] = NEG_INF;
        S->tix[j >> 5][j & 31] = -1;
    }
    if (tid < MQ) {
        S->thr[tid]     = NEG_INF;
        S->cand[0][tid] = 0ull;
        S->cand[1][tid] = 0ull;
    }

    const size_t kb = (size_t)b * L * D;

    // ---- prologue: load tile 0 synchronously + Mbits[0] ----
    for (int j = tid; j < 1024; j += THREADS) {
        int i  = j >> 4;
        int c4 = (j & 15) << 2;
        *(float4*)&S->Ks[0][i][c4] = *(const float4*)(k + kb + (size_t)i * D + c4);
        *(float4*)&S->Vs[0][i][c4] = *(const float4*)(v + kb + (size_t)i * D + c4);
    }
    if (tid < 512) {
        int qi = tid >> 4, c4 = (tid & 15) << 2;
        int4 mm = *(const int4*)(mask + (size_t)(row0 + qi) * L + c4);
        u64 bits = ((u64)(mm.x != 0) << c4)       | ((u64)(mm.y != 0) << (c4 + 1))
                 | ((u64)(mm.z != 0) << (c4 + 2)) | ((u64)(mm.w != 0) << (c4 + 3));
        #pragma unroll
        for (int off = 1; off < 16; off <<= 1)
            bits |= __shfl_xor_sync(0xFFFFFFFFu, bits, off);
        if ((tid & 15) == 0) S->Mbits[0][qi] = bits;
    }
    __syncthreads();

    u64 mv[8];                                  // V partial accumulators (4q x 4d)
    #pragma unroll
    for (int i = 0; i < 8; i++) mv[i] = 0ull;

    float thrL = NEG_INF;                       // merge warp state
    int   minpos = 0;
    float cntL = 0.0f;

    for (int t = 0; t < NT; t++) {
        const int p  = t & 1;
        const int pn = p ^ 1;
        const int l0 = t * TK;

        if (tid < 256) {
            // ======== score warps: 2q x 4k, strided k rows ========
            const float thr0 = S->thr[qa];
            const float thr1 = S->thr[qa + 1];
            const u64   Mb0  = S->Mbits[p][qa];
            const u64   Mb1  = S->Mbits[p][qa + 1];
            u64 sp0[4], sp1[4];
            #pragma unroll
            for (int j = 0; j < 4; j++) { sp0[j] = 0ull; sp1[j] = 0ull; }

            #pragma unroll 4
            for (int d = 0; d < D; d += 4) {
                ulonglong2 Q0 = *(const ulonglong2*)&S->Qs[qa][d];
                ulonglong2 Q1 = *(const ulonglong2*)&S->Qs[qa + 1][d];
                #pragma unroll
                for (int j = 0; j < 4; j++) {
                    ulonglong2 Kj = *(const ulonglong2*)&S->Ks[p][t15 + 16 * j][d];
                    fma2(sp0[j], Q0.x, Kj.x);
                    fma2(sp0[j], Q0.y, Kj.y);
                    fma2(sp1[j], Q1.x, Kj.x);
                    fma2(sp1[j], Q1.y, Kj.y);
                }
            }
            u64 w0 = 0ull, w1 = 0ull;
            #pragma unroll
            for (int j = 0; j < 4; j++) {
                int kp = t15 + 16 * j;
                float2 p0 = up2(sp0[j]);
                float  s0 = p0.x + p0.y;
                S->Ss[p][qa][kp] = s0;
                if (s0 > thr0 && ((Mb0 >> kp) & 1ull)) w0 |= 1ull << kp;
                float2 p1 = up2(sp1[j]);
                float  s1 = p1.x + p1.y;
                S->Ss[p][qa + 1][kp] = s1;
                if (s1 > thr1 && ((Mb1 >> kp) & 1ull)) w1 |= 1ull << kp;
            }
            if (w0) atomicOr(&S->cand[p][qa],     w0);
            if (w1) atomicOr(&S->cand[p][qa + 1], w1);
        } else if (tid < 512) {
            // ======== V warps: 4q x 4d over compile-time 32-key half ========
            unsigned mw[4];
            #pragma unroll
            for (int qi = 0; qi < 4; qi++) {
                u64 M = S->Mbits[p][qb + qi];
                mw[qi] = vhalf ? (unsigned)(M >> 32) : (unsigned)M;
            }
            const float* vrow = &S->Vs[p][vhalf << 5][dc];   // lbase folded once
            #pragma unroll
            for (int l = 0; l < 32; l++) {
                ulonglong2 v2 = *(const ulonglong2*)(vrow + (size_t)l * D);
                #pragma unroll
                for (int qi = 0; qi < 4; qi++) {
                    unsigned tb = mw[qi] & (1u << l);
                    madd2(mv[2 * qi], mv[2 * qi + 1], tb, v2.x, v2.y);
                }
            }
        } else if (tid < 544) {
            // ======== merge warp: consume tile t-1, prefetch mask t+1 ========
            const int qq = tid - 512;
            if (t > 0) {
                u64 w = S->cand[pn][qq];
                S->cand[pn][qq] = 0ull;
                cntL += (float)__popcll(S->Mbits[pn][qq]);
                const int l0p = l0 - TK;
                while (w) {
                    int kk = __ffsll((long long)w) - 1;
                    w &= w - 1ull;
                    float s = S->Ss[pn][qq][kk];
                    if (s > thrL) {
                        S->tsc[qq][minpos] = s;
                        S->tix[qq][minpos] = l0p + kk;
                        float nm = S->tsc[qq][0]; int np = 0;
                        #pragma unroll
                        for (int i = 1; i < TOPK; i++) {
                            float ti = S->tsc[qq][i];
                            if (ti < nm) { nm = ti; np = i; }
                        }
                        thrL = nm; minpos = np;
                    }
                }
                S->thr[qq] = thrL;
            }
            if (t < NT - 1) {
                const int4* mp = (const int4*)(mask + (size_t)(row0 + qq) * L + l0 + TK);
                u64 bits = 0ull;
                #pragma unroll
                for (int c4 = 0; c4 < 16; c4++) {
                    int4 mm = mp[c4];
                    bits |= ((u64)(mm.x != 0) << (4 * c4))
                          | ((u64)(mm.y != 0) << (4 * c4 + 1))
                          | ((u64)(mm.z != 0) << (4 * c4 + 2))
                          | ((u64)(mm.w != 0) << (4 * c4 + 3));
                }
                S->Mbits[pn][qq] = bits;
            }
        } else {
            // ======== loader warps: cp.async next K/V tile ========
            if (t < NT - 1) {
                const int lt = tid - 544;                  // 0..95
                const size_t base = kb + (size_t)(l0 + TK) * D;
                for (int j = lt; j < 2048; j += 96) {
                    int jj = j & 1023;
                    int i  = jj >> 4;
                    int c4 = (jj & 15) << 2;
                    if (j < 1024) cp16(&S->Ks[pn][i][c4], k + base + (size_t)i * D + c4);
                    else          cp16(&S->Vs[pn][i][c4], v + base + (size_t)i * D + c4);
                }
                asm volatile("cp.async.commit_group;");
                asm volatile("cp.async.wait_group 0;");
            }
        }
        __syncthreads();
    }

    // ---- final merge (last tile) ----
    if (tid >= 512 && tid < 544) {
        const int qq = tid - 512;
        const int pl = (NT - 1) & 1;
        u64 w = S->cand[pl][qq];
        cntL += (float)__popcll(S->Mbits[pl][qq]);
        const int l0p = L - TK;
        while (w) {
            int kk = __ffsll((long long)w) - 1;
            w &= w - 1ull;
            float s = S->Ss[pl][qq][kk];
            if (s > thrL) {
                S->tsc[qq][minpos] = s;
                S->tix[qq][minpos] = l0p + kk;
                float nm = S->tsc[qq][0]; int np = 0;
                #pragma unroll
                for (int i = 1; i < TOPK; i++) {
                    float ti = S->tsc[qq][i];
                    if (ti < nm) { nm = ti; np = i; }
                }
                thrL = nm; minpos = np;
            }
        }
        S->cnt[qq] = cntL;
    }
    __syncthreads();   // Ss[] free after this point

    // ---- combine V partials into Ss[0][q][d]: half 0 writes, half 1 adds ----
    if (tid >= 256 && tid < 384) {
        #pragma unroll
        for (int qi = 0; qi < 4; qi++) {
            float2 a = up2(mv[2 * qi]);
            float2 c = up2(mv[2 * qi + 1]);
            *(float4*)&S->Ss[0][qb + qi][dc] = make_float4(a.x, a.y, c.x, c.y);
        }
    }
    __syncthreads();
    if (tid >= 384 && tid < 512) {
        #pragma unroll
        for (int qi = 0; qi < 4; qi++) {
            float4 cur = *(float4*)&S->Ss[0][qb + qi][dc];
            float2 a = up2(mv[2 * qi]);
            float2 c = up2(mv[2 * qi + 1]);
            cur.x += a.x; cur.y += a.y; cur.z += c.x; cur.w += c.y;
            *(float4*)&S->Ss[0][qb + qi][dc] = cur;
        }
    }
    __syncthreads();

    // ---- epilogue: softmax over top-32, gather V, add mean ----
    const int wid  = tid >> 5;
    const int lane = tid & 31;
    const float* vb = v + kb;
    for (int qq = wid; qq < MQ; qq += (THREADS / 32)) {
        float s  = S->tsc[qq][lane];
        int   ix = S->tix[qq][lane];
        bool valid = (ix >= 0);
        float sv = valid ? s : NEG_INF;
        float m = sv;
        #pragma unroll
        for (int off = 16; off > 0; off >>= 1)
            m = fmaxf(m, __shfl_xor_sync(0xFFFFFFFFu, m, off));
        float e = valid ? expf(s - m) : 0.0f;
        float den = e;
        #pragma unroll
        for (int off = 16; off > 0; off >>= 1)
            den += __shfl_xor_sync(0xFFFFFFFFu, den, off);
        float w = (den > 0.0f) ? (e / den) : 0.0f;

        float a0 = 0.0f, a1 = 0.0f;
        #pragma unroll 1
        for (int i = 0; i < TOPK; i++) {
            float wi = __shfl_sync(0xFFFFFFFFu, w, i);
            int   ii = __shfl_sync(0xFFFFFFFFu, ix, i);
            if (ii >= 0) {
                const float* vr = vb + (size_t)ii * D;
                a0 = fmaf(wi, vr[lane],      a0);
                a1 = fmaf(wi, vr[lane + 32], a1);
            }
        }
        float c = fmaxf(S->cnt[qq], 1.0f);
        size_t obase = ((size_t)(row0 + qq)) * D;
        out[obase + lane]      = S->Ss[0][qq][lane]      / c + a0;
        out[obase + lane + 32] = S->Ss[0][qq][lane + 32] / c + a1;
    }
}

extern "C" void kernel_launch(void* const* d_in, const int* in_sizes, int n_in,
                              void* d_out, int out_size)
{
    const float* q = (const float*)d_in[0];
    const float* k = (const float*)d_in[1];
    const float* v = (const float*)d_in[2];
    const int*   mask = (const int*)d_in[3];
    float* out = (float*)d_out;

    int N    = in_sizes[0] / D;    // B * Lq
    int Ktot = in_sizes[1] / D;    // B * L
    int L    = in_sizes[3] / N;
    int B    = Ktot / L;
    int Lq   = N / B;

    int smem = (int)sizeof(Smem);
    cudaFuncSetAttribute(ga_kernel, cudaFuncAttributeMaxDynamicSharedMemorySize, smem);

    dim3 grid(Lq / MQ, B);
    ga_kernel<<<grid, THREADS, smem>>>(q, k, v, mask, out, B, Lq, L);
}